// round 2
// baseline (speedup 1.0000x reference)
#include <cuda_runtime.h>

// BKT_RNN: B=8192 rows, T=2048 sequential steps, H=4, X=1.
// One thread per batch row; weights register-resident.
// R2: software-pipelined chunk loads (register double-buffer) + paired
// reciprocals (2 sigmoids share one MUFU rcp) + streaming ld/st.

#define TT 2048
#define BB 8192

__device__ double g_loss_acc;

__global__ void k_zero() { g_loss_acc = 0.0; }

__device__ __forceinline__ float ex2f(float v) {
    float r; asm("ex2.approx.f32 %0, %1;" : "=f"(r) : "f"(v)); return r;
}
__device__ __forceinline__ float rcpf(float v) {
    float r; asm("rcp.approx.f32 %0, %1;" : "=f"(r) : "f"(v)); return r;
}
__device__ __forceinline__ float lg2f(float v) {
    float r; asm("lg2.approx.f32 %0, %1;" : "=f"(r) : "f"(v)); return r;
}

// Two sigmoids sharing one rcp: si = 1/(1+ei), ei = ex2(zi) (zi pre-scaled
// by -log2e). r = rcp(d0*d1); s0 = r*d1; s1 = r*d0.
__device__ __forceinline__ void sigpair(float z0, float z1, float& s0, float& s1) {
    const float e0 = ex2f(z0), e1 = ex2f(z1);
    const float d0 = 1.f + e0, d1 = 1.f + e1;
    const float r  = rcpf(d0 * d1);
    s0 = r * d1;
    s1 = r * d0;
}

__global__ void __launch_bounds__(32) k_bkt(
    const float* __restrict__ x,   const float* __restrict__ y,
    const float* __restrict__ Wxh, const float* __restrict__ Whh,
    const float* __restrict__ bh,  const float* __restrict__ Wy,
    const float* __restrict__ by,  const float* __restrict__ prior,
    float* __restrict__ corrects,  float* __restrict__ latents)
{
    const int b = blockIdx.x * 32 + threadIdx.x;

    // Pre-scale all weights by -log2(e): sigmoid(z) = rcp(1 + ex2(z')).
    const float NL2E = -1.4426950408889634f;
    float A[4][4], av[4];      // scaled Wy, by   (p-head)
    float Wh[4][4], bhv[4];    // scaled Whh, bh  (h recurrence)
    float wx[4];               // scaled Wxh
    #pragma unroll
    for (int j = 0; j < 4; j++) {
        av[j]  = NL2E * __ldg(by  + j);
        bhv[j] = NL2E * __ldg(bh  + j);
        wx[j]  = NL2E * __ldg(Wxh + j);
        #pragma unroll
        for (int i = 0; i < 4; i++) {
            A[i][j]  = NL2E * __ldg(Wy  + i * 4 + j);
            Wh[i][j] = NL2E * __ldg(Whh + i * 4 + j);
        }
    }

    float h0 = 0.f, h1 = 0.f, h2 = 0.f, h3 = 0.f;
    float lat  = __ldg(prior);
    float lsum = 0.f;

    const float4* xp = (const float4*)(x + (size_t)b * TT);
    const float4* yp = (const float4*)(y + (size_t)b * TT);
    float4* cp = (float4*)(corrects + (size_t)b * TT);
    float4* lp = (float4*)(latents  + (size_t)b * TT);

    // Prime the pipeline: chunk 0 loads.
    float4 xa = __ldcs(xp + 0), xb = __ldcs(xp + 1);
    float4 ya = __ldcs(yp + 0), yb = __ldcs(yp + 1);

    const int NCHUNK = TT / 8;
    for (int c = 0; c < NCHUNK; ++c) {
        const int t4 = 2 * c;

        // Stage current chunk into scalars.
        float xv[8] = {xa.x, xa.y, xa.z, xa.w, xb.x, xb.y, xb.z, xb.w};
        float yv[8] = {ya.x, ya.y, ya.z, ya.w, yb.x, yb.y, yb.z, yb.w};

        // Prefetch next chunk (overlaps with the 8-step compute below).
        if (c + 1 < NCHUNK) {
            xa = __ldcs(xp + t4 + 2); xb = __ldcs(xp + t4 + 3);
            ya = __ldcs(yp + t4 + 2); yb = __ldcs(yp + t4 + 3);
        }

        float cb[8], lb[8];

        #pragma unroll
        for (int k = 0; k < 8; k++) {
            // p = sigmoid(h @ Wy + by), paired rcp.
            float z[4];
            #pragma unroll
            for (int j = 0; j < 4; j++) {
                float zz = av[j];
                zz = fmaf(h0, A[0][j], zz);
                zz = fmaf(h1, A[1][j], zz);
                zz = fmaf(h2, A[2][j], zz);
                zz = fmaf(h3, A[3][j], zz);
                z[j] = zz;
            }
            float l_, f_, g_, s_;
            sigpair(z[0], z[1], l_, f_);
            sigpair(z[2], z[3], g_, s_);

            // BKT latent update. k_t1*correct == lat*(1-s) exactly -> 1 rcp.
            const float oml     = 1.f - lat;
            const float a       = lat * (1.f - s_);
            const float correct = fmaf(oml, g_, a);
            const float ls      = lat * s_;
            const float den0    = fmaf(oml, 1.f - g_, ls);
            const float k0      = ls * rcpf(den0);
            const float m       = fmaf(k0, 1.f - correct, a);
            lat = fmaf(m, 1.f - f_ - l_, l_);   // m*(1-f) + (1-m)*l

            // h_new = sigmoid(x_t*Wxh + h@Whh + bh)  (uses OLD h)
            const float xt = xv[k];
            float n0 = fmaf(xt, wx[0], bhv[0]);
            float n1 = fmaf(xt, wx[1], bhv[1]);
            float n2 = fmaf(xt, wx[2], bhv[2]);
            float n3 = fmaf(xt, wx[3], bhv[3]);
            n0 = fmaf(h0, Wh[0][0], n0); n1 = fmaf(h0, Wh[0][1], n1);
            n2 = fmaf(h0, Wh[0][2], n2); n3 = fmaf(h0, Wh[0][3], n3);
            n0 = fmaf(h1, Wh[1][0], n0); n1 = fmaf(h1, Wh[1][1], n1);
            n2 = fmaf(h1, Wh[1][2], n2); n3 = fmaf(h1, Wh[1][3], n3);
            n0 = fmaf(h2, Wh[2][0], n0); n1 = fmaf(h2, Wh[2][1], n1);
            n2 = fmaf(h2, Wh[2][2], n2); n3 = fmaf(h2, Wh[2][3], n3);
            n0 = fmaf(h3, Wh[3][0], n0); n1 = fmaf(h3, Wh[3][1], n1);
            n2 = fmaf(h3, Wh[3][2], n2); n3 = fmaf(h3, Wh[3][3], n3);
            sigpair(n0, n1, h0, h1);
            sigpair(n2, n3, h2, h3);

            // Loss: y in {0,1} exactly -> single log.
            const float cc  = fminf(fmaxf(correct, 1e-7f), 1.0f - 1e-7f);
            const float sel = (yv[k] != 0.f) ? cc : (1.f - cc);
            lsum += lg2f(sel);

            cb[k] = correct;
            lb[k] = lat;
        }

        __stcs(cp + t4,     make_float4(cb[0], cb[1], cb[2], cb[3]));
        __stcs(cp + t4 + 1, make_float4(cb[4], cb[5], cb[6], cb[7]));
        __stcs(lp + t4,     make_float4(lb[0], lb[1], lb[2], lb[3]));
        __stcs(lp + t4 + 1, make_float4(lb[4], lb[5], lb[6], lb[7]));
    }

    // Warp reduce + one double atomic per warp.
    #pragma unroll
    for (int o = 16; o > 0; o >>= 1)
        lsum += __shfl_xor_sync(0xffffffffu, lsum, o);
    if ((threadIdx.x & 31) == 0)
        atomicAdd(&g_loss_acc, (double)lsum);
}

__global__ void k_final(float* __restrict__ loss) {
    loss[0] = (float)(-0.6931471805599453 * g_loss_acc / ((double)BB * (double)TT));
}

extern "C" void kernel_launch(void* const* d_in, const int* in_sizes, int n_in,
                              void* d_out, int out_size) {
    const float* x     = (const float*)d_in[0];
    const float* y     = (const float*)d_in[1];
    const float* Wxh   = (const float*)d_in[2];
    const float* Whh   = (const float*)d_in[3];
    const float* bh    = (const float*)d_in[4];
    const float* Wy    = (const float*)d_in[5];
    const float* by    = (const float*)d_in[6];
    const float* prior = (const float*)d_in[7];

    float* corrects = (float*)d_out;
    float* latents  = (float*)d_out + (size_t)BB * TT;
    float* loss     = (float*)d_out + 2 * (size_t)BB * TT;

    k_zero<<<1, 1>>>();
    k_bkt<<<BB / 32, 32>>>(x, y, Wxh, Whh, bh, Wy, by, prior, corrects, latents);
    k_final<<<1, 1>>>(loss);
}

// round 3
// speedup vs baseline: 1.6097x; 1.6097x over previous
#include <cuda_runtime.h>

// BKT_RNN: B=8192, T=2048, H=4, X=1.
// R3: 4 lanes cooperate per row (lane j owns h_j and weight columns j).
// 1024 warps -> every SMSP occupied (~1.75 warps each) for latency hiding.
// Latent update computed redundantly (identically) on all 4 lanes.

#define TT 2048
#define BB 8192

__device__ double g_loss_acc;

__global__ void k_zero() { g_loss_acc = 0.0; }

__device__ __forceinline__ float ex2f(float v) {
    float r; asm("ex2.approx.f32 %0, %1;" : "=f"(r) : "f"(v)); return r;
}
__device__ __forceinline__ float rcpf(float v) {
    float r; asm("rcp.approx.f32 %0, %1;" : "=f"(r) : "f"(v)); return r;
}
__device__ __forceinline__ float lg2f(float v) {
    float r; asm("lg2.approx.f32 %0, %1;" : "=f"(r) : "f"(v)); return r;
}

__global__ void __launch_bounds__(32) k_bkt(
    const float* __restrict__ x,   const float* __restrict__ y,
    const float* __restrict__ Wxh, const float* __restrict__ Whh,
    const float* __restrict__ bh,  const float* __restrict__ Wy,
    const float* __restrict__ by,  const float* __restrict__ prior,
    float* __restrict__ corrects,  float* __restrict__ latents)
{
    const unsigned FULL = 0xffffffffu;
    const int j = threadIdx.x & 3;                 // unit index within row
    const int b = blockIdx.x * 8 + (threadIdx.x >> 2);  // row index

    // Lane j holds column j of the (pre-scaled) weights.
    // Pre-scale by -log2(e): sigmoid(z) = rcp(1 + ex2(z_scaled)).
    const float NL2E = -1.4426950408889634f;
    float Ac[4], Wc[4];
    #pragma unroll
    for (int i = 0; i < 4; i++) {
        Ac[i] = NL2E * __ldg(Wy  + i * 4 + j);
        Wc[i] = NL2E * __ldg(Whh + i * 4 + j);
    }
    const float avj = NL2E * __ldg(by  + j);
    const float bhj = NL2E * __ldg(bh  + j);
    const float wxj = NL2E * __ldg(Wxh + j);

    float hj   = 0.f;              // this lane's hidden unit
    float lat  = __ldg(prior);     // replicated across the 4 lanes
    float lsum = 0.f;

    const float4* xp = (const float4*)(x + (size_t)b * TT);
    const float4* yp = (const float4*)(y + (size_t)b * TT);
    float2* cp = (float2*)(corrects + (size_t)b * TT);
    float2* lp = (float2*)(latents  + (size_t)b * TT);

    // Prime pipeline: chunk 0 (8 timesteps) loads. All 4 lanes load the same
    // address -> broadcast; per-warp 8 distinct 16B segments = coalesced.
    float4 xa = __ldcs(xp + 0), xb = __ldcs(xp + 1);
    float4 ya = __ldcs(yp + 0), yb = __ldcs(yp + 1);

    const int NCHUNK = TT / 8;
    for (int c = 0; c < NCHUNK; ++c) {
        float xv[8] = {xa.x, xa.y, xa.z, xa.w, xb.x, xb.y, xb.z, xb.w};
        float yv[8] = {ya.x, ya.y, ya.z, ya.w, yb.x, yb.y, yb.z, yb.w};

        if (c + 1 < NCHUNK) {      // prefetch next chunk under compute
            xa = __ldcs(xp + 2 * c + 2); xb = __ldcs(xp + 2 * c + 3);
            ya = __ldcs(yp + 2 * c + 2); yb = __ldcs(yp + 2 * c + 3);
        }

        float cb[8], lb[8];

        #pragma unroll
        for (int k = 0; k < 8; k++) {
            // Gather full h vector from the 4-lane group.
            const float h0 = __shfl_sync(FULL, hj, 0, 4);
            const float h1 = __shfl_sync(FULL, hj, 1, 4);
            const float h2 = __shfl_sync(FULL, hj, 2, 4);
            const float h3 = __shfl_sync(FULL, hj, 3, 4);

            // p_j = sigmoid(h @ Wy[:,j] + by[j])   (one sigmoid per lane)
            float z = avj;
            z = fmaf(h0, Ac[0], z);
            z = fmaf(h1, Ac[1], z);
            z = fmaf(h2, Ac[2], z);
            z = fmaf(h3, Ac[3], z);
            const float pj = rcpf(1.f + ex2f(z));

            // Gather p -> (l, f, g, s) on every lane.
            const float l_ = __shfl_sync(FULL, pj, 0, 4);
            const float f_ = __shfl_sync(FULL, pj, 1, 4);
            const float g_ = __shfl_sync(FULL, pj, 2, 4);
            const float s_ = __shfl_sync(FULL, pj, 3, 4);

            // BKT latent update (identical on all lanes).
            // k_t1*correct == lat*(1-s) exactly -> single rcp.
            const float oml     = 1.f - lat;
            const float a       = lat * (1.f - s_);
            const float correct = fmaf(oml, g_, a);
            const float ls      = lat * s_;
            const float den0    = fmaf(oml, 1.f - g_, ls);
            const float r       = rcpf(den0);          // starts early
            const float m_      = fmaf(ls * r, 1.f - correct, a);
            lat = fmaf(m_, 1.f - f_ - l_, l_);         // m(1-f)+(1-m)l

            // h_j' = sigmoid(x_t*Wxh[j] + h @ Whh[:,j] + bh[j])  (OLD h)
            float zh = fmaf(xv[k], wxj, bhj);
            zh = fmaf(h0, Wc[0], zh);
            zh = fmaf(h1, Wc[1], zh);
            zh = fmaf(h2, Wc[2], zh);
            zh = fmaf(h3, Wc[3], zh);
            hj = rcpf(1.f + ex2f(zh));

            // Loss: y in {0,1} -> single log. All lanes accumulate the same
            // value (row counted 4x; corrected in k_final).
            const float cc  = fminf(fmaxf(correct, 1e-7f), 1.0f - 1e-7f);
            const float sel = (yv[k] != 0.f) ? cc : (1.f - cc);
            lsum += lg2f(sel);

            cb[k] = correct;
            lb[k] = lat;
        }

        // Lane j stores elements {2j, 2j+1} -> 32B contiguous per group,
        // 8 full sectors per warp store.
        const float ce0 = (j & 2) ? ((j & 1) ? cb[6] : cb[4])
                                  : ((j & 1) ? cb[2] : cb[0]);
        const float ce1 = (j & 2) ? ((j & 1) ? cb[7] : cb[5])
                                  : ((j & 1) ? cb[3] : cb[1]);
        const float le0 = (j & 2) ? ((j & 1) ? lb[6] : lb[4])
                                  : ((j & 1) ? lb[2] : lb[0]);
        const float le1 = (j & 2) ? ((j & 1) ? lb[7] : lb[5])
                                  : ((j & 1) ? lb[3] : lb[1]);
        __stcs(cp + c * 4 + j, make_float2(ce0, ce1));
        __stcs(lp + c * 4 + j, make_float2(le0, le1));
    }

    // Warp reduce (each row counted 4x) + one double atomic per warp.
    #pragma unroll
    for (int o = 16; o > 0; o >>= 1)
        lsum += __shfl_xor_sync(FULL, lsum, o);
    if ((threadIdx.x & 31) == 0)
        atomicAdd(&g_loss_acc, (double)lsum);
}

__global__ void k_final(float* __restrict__ loss) {
    // Each row accumulated 4x (once per lane).
    loss[0] = (float)(-0.6931471805599453 * g_loss_acc /
                      (4.0 * (double)BB * (double)TT));
}

extern "C" void kernel_launch(void* const* d_in, const int* in_sizes, int n_in,
                              void* d_out, int out_size) {
    const float* x     = (const float*)d_in[0];
    const float* y     = (const float*)d_in[1];
    const float* Wxh   = (const float*)d_in[2];
    const float* Whh   = (const float*)d_in[3];
    const float* bh    = (const float*)d_in[4];
    const float* Wy    = (const float*)d_in[5];
    const float* by    = (const float*)d_in[6];
    const float* prior = (const float*)d_in[7];

    float* corrects = (float*)d_out;
    float* latents  = (float*)d_out + (size_t)BB * TT;
    float* loss     = (float*)d_out + 2 * (size_t)BB * TT;

    k_zero<<<1, 1>>>();
    k_bkt<<<BB / 8, 32>>>(x, y, Wxh, Whh, bh, Wy, by, prior, corrects, latents);
    k_final<<<1, 1>>>(loss);
}

// round 4
// speedup vs baseline: 1.9763x; 1.2278x over previous
#include <cuda_runtime.h>

// BKT_RNN: B=8192, T=2048, H=4, X=1.
// R4: closed-form BKT latent update. Algebraic identity:
//   1-correct == lat*s + (1-lat)*(1-g)  (the k_t0 denominator), hence
//   m_t == latent exactly, so:
//     new_latent = lat*(1-f-l) + l     (one FMA, no division)
//     correct    = lat*(1-s-g) + g     (one FMA)
// Critical path is now only the h-recurrence. 4 lanes per row as in R3.
// Loss lg2 amortized over 4 steps via product accumulation.

#define TT 2048
#define BB 8192

__device__ double g_loss_acc;

__global__ void k_zero() { g_loss_acc = 0.0; }

__device__ __forceinline__ float ex2f(float v) {
    float r; asm("ex2.approx.f32 %0, %1;" : "=f"(r) : "f"(v)); return r;
}
__device__ __forceinline__ float rcpf(float v) {
    float r; asm("rcp.approx.f32 %0, %1;" : "=f"(r) : "f"(v)); return r;
}
__device__ __forceinline__ float lg2f(float v) {
    float r; asm("lg2.approx.f32 %0, %1;" : "=f"(r) : "f"(v)); return r;
}

__global__ void __launch_bounds__(32) k_bkt(
    const float* __restrict__ x,   const float* __restrict__ y,
    const float* __restrict__ Wxh, const float* __restrict__ Whh,
    const float* __restrict__ bh,  const float* __restrict__ Wy,
    const float* __restrict__ by,  const float* __restrict__ prior,
    float* __restrict__ corrects,  float* __restrict__ latents)
{
    const unsigned FULL = 0xffffffffu;
    const int j = threadIdx.x & 3;                      // unit index
    const int b = blockIdx.x * 8 + (threadIdx.x >> 2);  // row index

    // Lane j holds column j of the weights, pre-scaled by -log2(e):
    // sigmoid(z) = rcp(1 + ex2(z_scaled)).
    const float NL2E = -1.4426950408889634f;
    float Ac[4], Wc[4];
    #pragma unroll
    for (int i = 0; i < 4; i++) {
        Ac[i] = NL2E * __ldg(Wy  + i * 4 + j);
        Wc[i] = NL2E * __ldg(Whh + i * 4 + j);
    }
    const float avj = NL2E * __ldg(by  + j);
    const float bhj = NL2E * __ldg(bh  + j);
    const float wxj = NL2E * __ldg(Wxh + j);

    float hj   = 0.f;
    float lat  = __ldg(prior);   // replicated across the 4 lanes
    float lsum = 0.f;

    const float4* xp = (const float4*)(x + (size_t)b * TT);
    const float4* yp = (const float4*)(y + (size_t)b * TT);
    float2* cp = (float2*)(corrects + (size_t)b * TT);
    float2* lp = (float2*)(latents  + (size_t)b * TT);

    // Prime pipeline (chunk 0 = 8 timesteps). 4 lanes share the address ->
    // broadcast; 8 distinct 16B segments per warp = coalesced.
    float4 xa = __ldcs(xp + 0), xb = __ldcs(xp + 1);
    float4 ya = __ldcs(yp + 0), yb = __ldcs(yp + 1);

    const int NCHUNK = TT / 8;
    for (int c = 0; c < NCHUNK; ++c) {
        float xv[8] = {xa.x, xa.y, xa.z, xa.w, xb.x, xb.y, xb.z, xb.w};
        float yv[8] = {ya.x, ya.y, ya.z, ya.w, yb.x, yb.y, yb.z, yb.w};

        if (c + 1 < NCHUNK) {   // prefetch next chunk under compute
            xa = __ldcs(xp + 2 * c + 2); xb = __ldcs(xp + 2 * c + 3);
            ya = __ldcs(yp + 2 * c + 2); yb = __ldcs(yp + 2 * c + 3);
        }

        float cb[8], lb[8];
        float prod = 1.f;

        #pragma unroll
        for (int k = 0; k < 8; k++) {
            // Gather full h vector (4-lane group).
            const float h0 = __shfl_sync(FULL, hj, 0, 4);
            const float h1 = __shfl_sync(FULL, hj, 1, 4);
            const float h2 = __shfl_sync(FULL, hj, 2, 4);
            const float h3 = __shfl_sync(FULL, hj, 3, 4);

            // p_j = sigmoid(h @ Wy[:,j] + by[j])  — tree-shaped dot.
            const float zu = fmaf(h1, Ac[1], fmaf(h0, Ac[0], avj));
            const float zv = fmaf(h2, Ac[2], h3 * Ac[3]);
            const float pj = rcpf(1.f + ex2f(zu + zv));

            // h_j' = sigmoid(x*Wxh[j] + h @ Whh[:,j] + bh[j])  (OLD h).
            const float wu = fmaf(h0, Wc[0], fmaf(xv[k], wxj, bhj));
            const float wv = fmaf(h2, Wc[2], fmaf(h3, Wc[3], h1 * Wc[1]));
            hj = rcpf(1.f + ex2f(wu + wv));

            // Gather p = (l, f, g, s) to every lane.
            const float l_ = __shfl_sync(FULL, pj, 0, 4);
            const float f_ = __shfl_sync(FULL, pj, 1, 4);
            const float g_ = __shfl_sync(FULL, pj, 2, 4);
            const float s_ = __shfl_sync(FULL, pj, 3, 4);

            // Closed-form BKT update (exact): m_t == latent, so
            //   correct = lat*(1-s-g) + g ;  lat' = lat*(1-f-l) + l
            const float correct = fmaf(lat, 1.f - s_ - g_, g_);
            lat                 = fmaf(lat, 1.f - f_ - l_, l_);

            // Loss: y in {0,1} -> single selected factor; log every 4 steps.
            const float cc  = fminf(fmaxf(correct, 1e-7f), 1.0f - 1e-7f);
            const float sel = (yv[k] != 0.f) ? cc : (1.f - cc);
            prod *= sel;
            if ((k & 3) == 3) { lsum += lg2f(prod); prod = 1.f; }

            cb[k] = correct;
            lb[k] = lat;
        }

        // Lane j stores elements {2j, 2j+1}: 32B contiguous per group.
        const float ce0 = (j & 2) ? ((j & 1) ? cb[6] : cb[4])
                                  : ((j & 1) ? cb[2] : cb[0]);
        const float ce1 = (j & 2) ? ((j & 1) ? cb[7] : cb[5])
                                  : ((j & 1) ? cb[3] : cb[1]);
        const float le0 = (j & 2) ? ((j & 1) ? lb[6] : lb[4])
                                  : ((j & 1) ? lb[2] : lb[0]);
        const float le1 = (j & 2) ? ((j & 1) ? lb[7] : lb[5])
                                  : ((j & 1) ? lb[3] : lb[1]);
        __stcs(cp + c * 4 + j, make_float2(ce0, ce1));
        __stcs(lp + c * 4 + j, make_float2(le0, le1));
    }

    // Warp reduce (each row counted 4x) + one double atomic per warp.
    #pragma unroll
    for (int o = 16; o > 0; o >>= 1)
        lsum += __shfl_xor_sync(FULL, lsum, o);
    if ((threadIdx.x & 31) == 0)
        atomicAdd(&g_loss_acc, (double)lsum);
}

__global__ void k_final(float* __restrict__ loss) {
    loss[0] = (float)(-0.6931471805599453 * g_loss_acc /
                      (4.0 * (double)BB * (double)TT));
}

extern "C" void kernel_launch(void* const* d_in, const int* in_sizes, int n_in,
                              void* d_out, int out_size) {
    const float* x     = (const float*)d_in[0];
    const float* y     = (const float*)d_in[1];
    const float* Wxh   = (const float*)d_in[2];
    const float* Whh   = (const float*)d_in[3];
    const float* bh    = (const float*)d_in[4];
    const float* Wy    = (const float*)d_in[5];
    const float* by    = (const float*)d_in[6];
    const float* prior = (const float*)d_in[7];

    float* corrects = (float*)d_out;
    float* latents  = (float*)d_out + (size_t)BB * TT;
    float* loss     = (float*)d_out + 2 * (size_t)BB * TT;

    k_zero<<<1, 1>>>();
    k_bkt<<<BB / 8, 32>>>(x, y, Wxh, Whh, bh, Wy, by, prior, corrects, latents);
    k_final<<<1, 1>>>(loss);
}